// round 1
// baseline (speedup 1.0000x reference)
#include <cuda_runtime.h>

#define NN 50000
#define EE 800000
#define HH 3
#define INF 128
#define HIDN 128
#define HF (HH*HIDN)   // 384
#define NCLS 6

// ---------------- scratch (device globals; no allocation allowed) --------
__device__ float g_h[NN*HF];       // post-GEMM per-head features
__device__ float g_out[NN*HF];     // aggregated GAT output
__device__ float g_x[NN*HIDN];     // layer input / MLP ping
__device__ float g_y[NN*HIDN];     // MLP pong
__device__ float g_el[NN*HH];
__device__ float g_er[NN*HH];
__device__ float g_alpha[EE*HH];   // edge logits, then alpha in-place
__device__ int   g_deg[NN];
__device__ int   g_rowptr[NN+1];
__device__ int   g_wptr[NN];
__device__ int   g_eidx[EE];

// ---------------- CSR build ----------------------------------------------
__global__ void zero_deg_kernel() {
    int i = blockIdx.x*blockDim.x + threadIdx.x;
    if (i < NN) g_deg[i] = 0;
}

__global__ void hist_kernel(const int* __restrict__ dst) {
    int i = blockIdx.x*blockDim.x + threadIdx.x;
    if (i < EE) atomicAdd(&g_deg[dst[i]], 1);
}

__global__ void scan_kernel() {
    __shared__ int sh[1024];
    int t = threadIdx.x;
    const int ITEMS = (NN + 1023) / 1024;   // 49
    int base = t * ITEMS;
    int s = 0;
    for (int i = 0; i < ITEMS; i++) {
        int idx = base + i;
        if (idx < NN) s += g_deg[idx];
    }
    sh[t] = s;
    __syncthreads();
    for (int off = 1; off < 1024; off <<= 1) {
        int v = (t >= off) ? sh[t - off] : 0;
        __syncthreads();
        sh[t] += v;
        __syncthreads();
    }
    int run = sh[t] - s;   // exclusive prefix
    for (int i = 0; i < ITEMS; i++) {
        int idx = base + i;
        if (idx < NN) {
            g_rowptr[idx] = run;
            g_wptr[idx]   = run;
            run += g_deg[idx];
        }
    }
    if (t == 0) g_rowptr[NN] = EE;
}

__global__ void scatter_kernel(const int* __restrict__ dst) {
    int i = blockIdx.x*blockDim.x + threadIdx.x;
    if (i < EE) {
        int d = dst[i];
        int p = atomicAdd(&g_wptr[d], 1);
        g_eidx[p] = i;
    }
}

// ---------------- SGEMM: C = A(MxK) @ B(KxNcols) [+bias][+leaky 0.01] ----
// Requires Ncols % 64 == 0, K % 16 == 0 (true for 384 / 128 / 128).
__global__ void sgemm_kernel(const float* __restrict__ A, const float* __restrict__ B,
                             const float* __restrict__ bias, float* __restrict__ C,
                             int M, int Ncols, int K, int act)
{
    __shared__ float As[16][64];
    __shared__ float Bs[16][64];
    int tid = threadIdx.x;
    int tx = tid & 15, ty = tid >> 4;
    int row0 = blockIdx.y * 64, col0 = blockIdx.x * 64;
    float acc[4][4] = {};
    for (int k0 = 0; k0 < K; k0 += 16) {
        #pragma unroll
        for (int i = 0; i < 4; i++) {
            int q = tid + i * 256;
            int r = q >> 4, c = q & 15;      // As: 64 rows x 16 k
            int gr = row0 + r;
            As[c][r] = (gr < M) ? A[gr*K + k0 + c] : 0.f;
            int r2 = q >> 6, c2 = q & 63;    // Bs: 16 k x 64 cols
            Bs[r2][c2] = B[(k0 + r2)*Ncols + col0 + c2];
        }
        __syncthreads();
        #pragma unroll
        for (int kk = 0; kk < 16; kk++) {
            float a[4], b[4];
            #pragma unroll
            for (int i = 0; i < 4; i++) a[i] = As[kk][ty*4 + i];
            #pragma unroll
            for (int j = 0; j < 4; j++) b[j] = Bs[kk][tx*4 + j];
            #pragma unroll
            for (int i = 0; i < 4; i++)
                #pragma unroll
                for (int j = 0; j < 4; j++)
                    acc[i][j] += a[i]*b[j];
        }
        __syncthreads();
    }
    #pragma unroll
    for (int i = 0; i < 4; i++) {
        int r = row0 + ty*4 + i;
        if (r >= M) continue;
        #pragma unroll
        for (int j = 0; j < 4; j++) {
            int c = col0 + tx*4 + j;
            float v = acc[i][j];
            if (bias) v += bias[c];
            if (act)  v = v > 0.f ? v : 0.01f*v;
            C[r*Ncols + c] = v;
        }
    }
}

// ---------------- el/er: per-(node,head) dot with attn vectors -----------
__global__ void elr_kernel(const float* __restrict__ al, const float* __restrict__ ar)
{
    int gw   = (blockIdx.x*blockDim.x + threadIdx.x) >> 5;
    int lane = threadIdx.x & 31;
    if (gw >= NN*HH) return;
    int n = gw / HH, hh = gw % HH;
    const float* hr  = &g_h[n*HF + hh*HIDN];
    const float* alr = &al[hh*HIDN];
    const float* arr = &ar[hh*HIDN];
    float sl = 0.f, sr = 0.f;
    for (int k = lane; k < HIDN; k += 32) {
        float v = hr[k];
        sl += v * __ldg(&alr[k]);
        sr += v * __ldg(&arr[k]);
    }
    #pragma unroll
    for (int o = 16; o; o >>= 1) {
        sl += __shfl_xor_sync(0xffffffffu, sl, o);
        sr += __shfl_xor_sync(0xffffffffu, sr, o);
    }
    if (lane == 0) { g_el[gw] = sl; g_er[gw] = sr; }
}

// ---------------- edge logits: leaky_relu(el[src]+er[dst], 0.2) ----------
__global__ void edge_e_kernel(const int* __restrict__ src, const int* __restrict__ dst)
{
    int i = blockIdx.x*blockDim.x + threadIdx.x;
    if (i >= EE) return;
    int s = src[i], d = dst[i];
    #pragma unroll
    for (int hh = 0; hh < HH; hh++) {
        float v = g_el[s*HH + hh] + g_er[d*HH + hh];
        v = v > 0.f ? v : 0.2f*v;
        g_alpha[i*HH + hh] = v;
    }
}

// ---------------- edge softmax per (dst,head) via CSR, warp/segment ------
__global__ void edge_softmax_kernel()
{
    int gw   = (blockIdx.x*blockDim.x + threadIdx.x) >> 5;
    int lane = threadIdx.x & 31;
    if (gw >= NN*HH) return;
    int n = gw / HH, hh = gw % HH;
    int beg = g_rowptr[n], end = g_rowptr[n+1];
    if (beg == end) return;
    float mx = -1e30f;
    for (int j = beg + lane; j < end; j += 32)
        mx = fmaxf(mx, g_alpha[g_eidx[j]*HH + hh]);
    #pragma unroll
    for (int o = 16; o; o >>= 1) mx = fmaxf(mx, __shfl_xor_sync(0xffffffffu, mx, o));
    float s = 0.f;
    for (int j = beg + lane; j < end; j += 32)
        s += expf(g_alpha[g_eidx[j]*HH + hh] - mx);
    #pragma unroll
    for (int o = 16; o; o >>= 1) s += __shfl_xor_sync(0xffffffffu, s, o);
    float inv = 1.f / (s + 1e-9f);
    for (int j = beg + lane; j < end; j += 32) {
        int e = g_eidx[j];
        g_alpha[e*HH + hh] = expf(g_alpha[e*HH + hh] - mx) * inv;
    }
}

// ---------------- aggregation: out[dst] = sum alpha * h[src], +bias ------
__global__ void aggregate_kernel(const int* __restrict__ src, const float* __restrict__ bias)
{
    int n = blockIdx.x;
    int t = threadIdx.x;     // 128 threads, one feature each per head
    int beg = g_rowptr[n], end = g_rowptr[n+1];
    float a0 = 0.f, a1 = 0.f, a2 = 0.f;
    for (int j = beg; j < end; j++) {
        int e = g_eidx[j];
        int s = src[e];
        float w0 = __ldg(&g_alpha[e*HH + 0]);
        float w1 = __ldg(&g_alpha[e*HH + 1]);
        float w2 = __ldg(&g_alpha[e*HH + 2]);
        const float* hr = &g_h[s*HF];
        a0 += w0 * __ldg(&hr[t]);
        a1 += w1 * __ldg(&hr[HIDN + t]);
        a2 += w2 * __ldg(&hr[2*HIDN + t]);
    }
    g_out[n*HF + t]          = a0 + bias[t];
    g_out[n*HF + HIDN + t]   = a1 + bias[HIDN + t];
    g_out[n*HF + 2*HIDN + t] = a2 + bias[2*HIDN + t];
}

// ---------------- activation (0.01) + mean over heads --------------------
__global__ void actmean_kernel()
{
    int i = blockIdx.x*blockDim.x + threadIdx.x;
    if (i >= NN*HIDN) return;
    int n = i / HIDN, f = i % HIDN;
    const float* o = &g_out[n*HF];
    float s = 0.f;
    #pragma unroll
    for (int hh = 0; hh < HH; hh++) {
        float v = o[hh*HIDN + f];
        s += v > 0.f ? v : 0.01f*v;
    }
    g_x[i] = s * (1.f/3.f);
}

// ---------------- classifier: (N,128)@(128,6)+b, warp per node -----------
__global__ void classifier_kernel(const float* __restrict__ lw5, const float* __restrict__ lb5,
                                  float* __restrict__ out)
{
    int gw   = (blockIdx.x*blockDim.x + threadIdx.x) >> 5;
    int lane = threadIdx.x & 31;
    if (gw >= NN) return;
    const float* xr = &g_x[gw*HIDN];
    float acc[NCLS] = {};
    for (int k = lane; k < HIDN; k += 32) {
        float xv = xr[k];
        #pragma unroll
        for (int c = 0; c < NCLS; c++) acc[c] += xv * __ldg(&lw5[k*NCLS + c]);
    }
    #pragma unroll
    for (int c = 0; c < NCLS; c++)
        #pragma unroll
        for (int o = 16; o; o >>= 1) acc[c] += __shfl_xor_sync(0xffffffffu, acc[c], o);
    if (lane == 0) {
        #pragma unroll
        for (int c = 0; c < NCLS; c++) out[gw*NCLS + c] = acc[c] + lb5[c];
    }
}

// -------------------------------------------------------------------------
extern "C" void kernel_launch(void* const* d_in, const int* in_sizes, int n_in,
                              void* d_out, int out_size)
{
    const float* in_feat = (const float*)d_in[0];
    const int*   src     = (const int*)  d_in[1];
    const int*   dst     = (const int*)  d_in[2];
    const float* W1  = (const float*)d_in[3];
    const float* al1 = (const float*)d_in[4];
    const float* ar1 = (const float*)d_in[5];
    const float* b1  = (const float*)d_in[6];
    const float* W2  = (const float*)d_in[7];
    const float* al2 = (const float*)d_in[8];
    const float* ar2 = (const float*)d_in[9];
    const float* b2  = (const float*)d_in[10];
    const float* lw1 = (const float*)d_in[11];
    const float* lb1 = (const float*)d_in[12];
    const float* lw2 = (const float*)d_in[13];
    const float* lb2 = (const float*)d_in[14];
    const float* lw3 = (const float*)d_in[15];
    const float* lb3 = (const float*)d_in[16];
    const float* lw4 = (const float*)d_in[17];
    const float* lb4 = (const float*)d_in[18];
    const float* lw5 = (const float*)d_in[19];
    const float* lb5 = (const float*)d_in[20];
    float* out = (float*)d_out;

    float *ph, *px, *py;
    cudaGetSymbolAddress((void**)&ph, g_h);
    cudaGetSymbolAddress((void**)&px, g_x);
    cudaGetSymbolAddress((void**)&py, g_y);

    const int TB = 256;
    int warp_blocks = (NN*HH + 7) / 8;   // 8 warps per 256-thread block

    // CSR build (same for both layers)
    zero_deg_kernel<<<(NN + TB - 1)/TB, TB>>>();
    hist_kernel<<<(EE + TB - 1)/TB, TB>>>(dst);
    scan_kernel<<<1, 1024>>>();
    scatter_kernel<<<(EE + TB - 1)/TB, TB>>>(dst);

    dim3 g_gat(HF/64, (NN + 63)/64);
    dim3 g_mlp(HIDN/64, (NN + 63)/64);

    // ---- GAT layer 1 ----
    sgemm_kernel<<<g_gat, 256>>>(in_feat, W1, nullptr, ph, NN, HF, INF, 0);
    elr_kernel<<<warp_blocks, 256>>>(al1, ar1);
    edge_e_kernel<<<(EE + TB - 1)/TB, TB>>>(src, dst);
    edge_softmax_kernel<<<warp_blocks, 256>>>();
    aggregate_kernel<<<NN, 128>>>(src, b1);
    actmean_kernel<<<(NN*HIDN + TB - 1)/TB, TB>>>();

    // ---- GAT layer 2 ----
    sgemm_kernel<<<g_gat, 256>>>(px, W2, nullptr, ph, NN, HF, HIDN, 0);
    elr_kernel<<<warp_blocks, 256>>>(al2, ar2);
    edge_e_kernel<<<(EE + TB - 1)/TB, TB>>>(src, dst);
    edge_softmax_kernel<<<warp_blocks, 256>>>();
    aggregate_kernel<<<NN, 128>>>(src, b2);
    actmean_kernel<<<(NN*HIDN + TB - 1)/TB, TB>>>();

    // ---- MLP head ----
    sgemm_kernel<<<g_mlp, 256>>>(px, lw1, lb1, py, NN, HIDN, HIDN, 1);
    sgemm_kernel<<<g_mlp, 256>>>(py, lw2, lb2, px, NN, HIDN, HIDN, 1);
    sgemm_kernel<<<g_mlp, 256>>>(px, lw3, lb3, py, NN, HIDN, HIDN, 1);
    sgemm_kernel<<<g_mlp, 256>>>(py, lw4, lb4, px, NN, HIDN, HIDN, 1);
    classifier_kernel<<<(NN + 7)/8, 256>>>(lw5, lb5, out);
}

// round 2
// speedup vs baseline: 1.3182x; 1.3182x over previous
#include <cuda_runtime.h>

#define NN 50000
#define EE 800000
#define HH 3
#define INF 128
#define HIDN 128
#define HF (HH*HIDN)   // 384
#define NCLS 6

// ---------------- scratch (device globals; no allocation allowed) --------
__device__ float g_h[NN*HF];       // post-GEMM per-head features
__device__ float g_out[NN*HF];     // aggregated GAT output
__device__ float g_x[NN*HIDN];     // layer input / MLP ping
__device__ float g_y[NN*HIDN];     // MLP pong
__device__ float g_el[NN*HH];
__device__ float g_er[NN*HH];
__device__ float g_alpha[3*EE];    // planar: [h][csr_pos]
__device__ int   g_srcs[EE];       // src node id in CSR order
__device__ int   g_deg[NN];
__device__ int   g_rowptr[NN+1];
__device__ int   g_wptr[NN];

// ---------------- CSR build ----------------------------------------------
__global__ void zero_deg_kernel() {
    int i = blockIdx.x*blockDim.x + threadIdx.x;
    if (i < NN) g_deg[i] = 0;
}

__global__ void hist_kernel(const int* __restrict__ dst) {
    int i = blockIdx.x*blockDim.x + threadIdx.x;
    if (i < EE) atomicAdd(&g_deg[dst[i]], 1);
}

__global__ void scan_kernel() {
    __shared__ int sh[1024];
    int t = threadIdx.x;
    const int ITEMS = (NN + 1023) / 1024;   // 49
    int base = t * ITEMS;
    int s = 0;
    #pragma unroll 7
    for (int i = 0; i < ITEMS; i++) {
        int idx = base + i;
        if (idx < NN) s += g_deg[idx];
    }
    sh[t] = s;
    __syncthreads();
    for (int off = 1; off < 1024; off <<= 1) {
        int v = (t >= off) ? sh[t - off] : 0;
        __syncthreads();
        sh[t] += v;
        __syncthreads();
    }
    int run = sh[t] - s;   // exclusive prefix
    for (int i = 0; i < ITEMS; i++) {
        int idx = base + i;
        if (idx < NN) {
            g_rowptr[idx] = run;
            g_wptr[idx]   = run;
            run += g_deg[idx];
        }
    }
    if (t == 0) g_rowptr[NN] = EE;
}

__global__ void scatter_kernel(const int* __restrict__ src, const int* __restrict__ dst) {
    int i = blockIdx.x*blockDim.x + threadIdx.x;
    if (i < EE) {
        int d = dst[i];
        int p = atomicAdd(&g_wptr[d], 1);
        g_srcs[p] = src[i];
    }
}

// ---------------- SGEMM 128x128 tile, 8x8/thread, double-buffered --------
// C(MxNcols) = A(Mx128) @ B(128xNcols) [+bias][+leaky 0.01]; Ncols % 128 == 0.
__global__ __launch_bounds__(256, 2)
void sgemm128_kernel(const float* __restrict__ A, const float* __restrict__ B,
                     const float* __restrict__ bias, float* __restrict__ C,
                     int M, int Ncols, int act)
{
    __shared__ float As[2][16][128];   // k-major (transposed)
    __shared__ float Bs[2][16][128];
    int tid = threadIdx.x;
    int tx = tid & 15, ty = tid >> 4;
    int row0 = blockIdx.y * 128, col0 = blockIdx.x * 128;

    float acc[8][8] = {};
    const float4 z4 = make_float4(0.f, 0.f, 0.f, 0.f);

    // prologue: load k-tile 0 into buffer 0
    {
        #pragma unroll
        for (int i = 0; i < 2; i++) {
            int q = tid + i * 256;
            int r = q >> 2, c4 = q & 3;
            int gr = row0 + r;
            float4 av = (gr < M) ? *(const float4*)&A[gr*128 + c4*4] : z4;
            As[0][c4*4+0][r] = av.x;
            As[0][c4*4+1][r] = av.y;
            As[0][c4*4+2][r] = av.z;
            As[0][c4*4+3][r] = av.w;
            int kr = q >> 5, n4 = q & 31;
            float4 bv = *(const float4*)&B[kr*Ncols + col0 + n4*4];
            *(float4*)&Bs[0][kr][n4*4] = bv;
        }
    }
    __syncthreads();

    #pragma unroll
    for (int kt = 0; kt < 8; kt++) {
        int buf = kt & 1;
        float4 a_pref[2], b_pref[2];
        if (kt < 7) {
            int k0 = (kt + 1) * 16;
            #pragma unroll
            for (int i = 0; i < 2; i++) {
                int q = tid + i * 256;
                int r = q >> 2, c4 = q & 3;
                int gr = row0 + r;
                a_pref[i] = (gr < M) ? *(const float4*)&A[gr*128 + k0 + c4*4] : z4;
                int kr = q >> 5, n4 = q & 31;
                b_pref[i] = *(const float4*)&B[(k0 + kr)*Ncols + col0 + n4*4];
            }
        }
        #pragma unroll
        for (int k = 0; k < 16; k++) {
            float4 a0 = *(const float4*)&As[buf][k][ty*8];
            float4 a1 = *(const float4*)&As[buf][k][ty*8 + 4];
            float4 b0 = *(const float4*)&Bs[buf][k][tx*8];
            float4 b1 = *(const float4*)&Bs[buf][k][tx*8 + 4];
            float a[8] = {a0.x,a0.y,a0.z,a0.w,a1.x,a1.y,a1.z,a1.w};
            float b[8] = {b0.x,b0.y,b0.z,b0.w,b1.x,b1.y,b1.z,b1.w};
            #pragma unroll
            for (int i = 0; i < 8; i++)
                #pragma unroll
                for (int j = 0; j < 8; j++)
                    acc[i][j] += a[i]*b[j];
        }
        if (kt < 7) {
            int nbuf = buf ^ 1;
            #pragma unroll
            for (int i = 0; i < 2; i++) {
                int q = tid + i * 256;
                int r = q >> 2, c4 = q & 3;
                As[nbuf][c4*4+0][r] = a_pref[i].x;
                As[nbuf][c4*4+1][r] = a_pref[i].y;
                As[nbuf][c4*4+2][r] = a_pref[i].z;
                As[nbuf][c4*4+3][r] = a_pref[i].w;
                int kr = q >> 5, n4 = q & 31;
                *(float4*)&Bs[nbuf][kr][n4*4] = b_pref[i];
            }
            __syncthreads();
        }
    }

    // epilogue
    float bb[8];
    #pragma unroll
    for (int j = 0; j < 8; j++)
        bb[j] = bias ? bias[col0 + tx*8 + j] : 0.f;
    #pragma unroll
    for (int i = 0; i < 8; i++) {
        int r = row0 + ty*8 + i;
        if (r >= M) continue;
        float v[8];
        #pragma unroll
        for (int j = 0; j < 8; j++) {
            float t = acc[i][j] + bb[j];
            v[j] = act ? (t > 0.f ? t : 0.01f*t) : t;
        }
        *(float4*)&C[r*Ncols + col0 + tx*8]     = make_float4(v[0],v[1],v[2],v[3]);
        *(float4*)&C[r*Ncols + col0 + tx*8 + 4] = make_float4(v[4],v[5],v[6],v[7]);
    }
}

// ---------------- el/er: per-(node,head) dot with attn vectors -----------
__global__ void elr_kernel(const float* __restrict__ al, const float* __restrict__ ar)
{
    int gw   = (blockIdx.x*blockDim.x + threadIdx.x) >> 5;
    int lane = threadIdx.x & 31;
    if (gw >= NN*HH) return;
    int n = gw / HH, hh = gw % HH;
    const float* hr  = &g_h[n*HF + hh*HIDN];
    const float* alr = &al[hh*HIDN];
    const float* arr = &ar[hh*HIDN];
    float sl = 0.f, sr = 0.f;
    #pragma unroll
    for (int k = lane; k < HIDN; k += 32) {
        float v = hr[k];
        sl += v * __ldg(&alr[k]);
        sr += v * __ldg(&arr[k]);
    }
    #pragma unroll
    for (int o = 16; o; o >>= 1) {
        sl += __shfl_xor_sync(0xffffffffu, sl, o);
        sr += __shfl_xor_sync(0xffffffffu, sr, o);
    }
    if (lane == 0) { g_el[gw] = sl; g_er[gw] = sr; }
}

// ---------------- fused edge logits + softmax, warp per (dst,head) -------
// pass1: gather el[src]+er[dst], leaky(0.2), store CSR-planar, track max
// pass2: exp+sum (sequential, L1-hot)   pass3: scale
__global__ void edge_softmax_kernel()
{
    int gw   = (blockIdx.x*blockDim.x + threadIdx.x) >> 5;
    int lane = threadIdx.x & 31;
    if (gw >= NN*HH) return;
    int n = gw / HH, hh = gw % HH;
    int beg = g_rowptr[n], end = g_rowptr[n+1];
    if (beg == end) return;
    float er_n = g_er[n*HH + hh];
    float* ap = &g_alpha[hh*EE];
    float mx = -1e30f;
    for (int j = beg + lane; j < end; j += 32) {
        int s = g_srcs[j];
        float v = g_el[s*HH + hh] + er_n;
        v = v > 0.f ? v : 0.2f*v;
        ap[j] = v;
        mx = fmaxf(mx, v);
    }
    #pragma unroll
    for (int o = 16; o; o >>= 1) mx = fmaxf(mx, __shfl_xor_sync(0xffffffffu, mx, o));
    float s = 0.f;
    for (int j = beg + lane; j < end; j += 32)
        s += expf(ap[j] - mx);
    #pragma unroll
    for (int o = 16; o; o >>= 1) s += __shfl_xor_sync(0xffffffffu, s, o);
    float inv = 1.f / (s + 1e-9f);
    for (int j = beg + lane; j < end; j += 32)
        ap[j] = expf(ap[j] - mx) * inv;
}

// ---------------- aggregation: out[dst] = sum alpha * h[src], +bias ------
__global__ void aggregate_kernel(const float* __restrict__ bias)
{
    int n = blockIdx.x;
    int t = threadIdx.x;     // 128 threads, one feature per head
    int beg = g_rowptr[n], end = g_rowptr[n+1];
    float a0 = 0.f, a1 = 0.f, a2 = 0.f;
    for (int j = beg; j < end; j++) {
        int s = g_srcs[j];
        float w0 = __ldg(&g_alpha[j]);
        float w1 = __ldg(&g_alpha[EE + j]);
        float w2 = __ldg(&g_alpha[2*EE + j]);
        const float* hr = &g_h[s*HF];
        a0 += w0 * __ldg(&hr[t]);
        a1 += w1 * __ldg(&hr[HIDN + t]);
        a2 += w2 * __ldg(&hr[2*HIDN + t]);
    }
    g_out[n*HF + t]          = a0 + bias[t];
    g_out[n*HF + HIDN + t]   = a1 + bias[HIDN + t];
    g_out[n*HF + 2*HIDN + t] = a2 + bias[2*HIDN + t];
}

// ---------------- activation (0.01) + mean over heads --------------------
__global__ void actmean_kernel()
{
    int i = blockIdx.x*blockDim.x + threadIdx.x;
    if (i >= NN*HIDN) return;
    int n = i / HIDN, f = i % HIDN;
    const float* o = &g_out[n*HF];
    float s = 0.f;
    #pragma unroll
    for (int hh = 0; hh < HH; hh++) {
        float v = o[hh*HIDN + f];
        s += v > 0.f ? v : 0.01f*v;
    }
    g_x[i] = s * (1.f/3.f);
}

// ---------------- classifier: (N,128)@(128,6)+b, warp per node -----------
__global__ void classifier_kernel(const float* __restrict__ lw5, const float* __restrict__ lb5,
                                  float* __restrict__ out)
{
    int gw   = (blockIdx.x*blockDim.x + threadIdx.x) >> 5;
    int lane = threadIdx.x & 31;
    if (gw >= NN) return;
    const float* xr = &g_x[gw*HIDN];
    float acc[NCLS] = {};
    #pragma unroll
    for (int k = lane; k < HIDN; k += 32) {
        float xv = xr[k];
        #pragma unroll
        for (int c = 0; c < NCLS; c++) acc[c] += xv * __ldg(&lw5[k*NCLS + c]);
    }
    #pragma unroll
    for (int c = 0; c < NCLS; c++)
        #pragma unroll
        for (int o = 16; o; o >>= 1) acc[c] += __shfl_xor_sync(0xffffffffu, acc[c], o);
    if (lane == 0) {
        #pragma unroll
        for (int c = 0; c < NCLS; c++) out[gw*NCLS + c] = acc[c] + lb5[c];
    }
}

// -------------------------------------------------------------------------
extern "C" void kernel_launch(void* const* d_in, const int* in_sizes, int n_in,
                              void* d_out, int out_size)
{
    const float* in_feat = (const float*)d_in[0];
    const int*   src     = (const int*)  d_in[1];
    const int*   dst     = (const int*)  d_in[2];
    const float* W1  = (const float*)d_in[3];
    const float* al1 = (const float*)d_in[4];
    const float* ar1 = (const float*)d_in[5];
    const float* b1  = (const float*)d_in[6];
    const float* W2  = (const float*)d_in[7];
    const float* al2 = (const float*)d_in[8];
    const float* ar2 = (const float*)d_in[9];
    const float* b2  = (const float*)d_in[10];
    const float* lw1 = (const float*)d_in[11];
    const float* lb1 = (const float*)d_in[12];
    const float* lw2 = (const float*)d_in[13];
    const float* lb2 = (const float*)d_in[14];
    const float* lw3 = (const float*)d_in[15];
    const float* lb3 = (const float*)d_in[16];
    const float* lw4 = (const float*)d_in[17];
    const float* lb4 = (const float*)d_in[18];
    const float* lw5 = (const float*)d_in[19];
    const float* lb5 = (const float*)d_in[20];
    float* out = (float*)d_out;

    float *ph, *px, *py;
    cudaGetSymbolAddress((void**)&ph, g_h);
    cudaGetSymbolAddress((void**)&px, g_x);
    cudaGetSymbolAddress((void**)&py, g_y);

    const int TB = 256;
    int warp_blocks = (NN*HH + 7) / 8;   // 8 warps per 256-thread block

    // CSR build (shared by both layers)
    zero_deg_kernel<<<(NN + TB - 1)/TB, TB>>>();
    hist_kernel<<<(EE + TB - 1)/TB, TB>>>(dst);
    scan_kernel<<<1, 1024>>>();
    scatter_kernel<<<(EE + TB - 1)/TB, TB>>>(src, dst);

    dim3 g_gat(HF/128, (NN + 127)/128);
    dim3 g_mlp(HIDN/128, (NN + 127)/128);

    // ---- GAT layer 1 ----
    sgemm128_kernel<<<g_gat, 256>>>(in_feat, W1, nullptr, ph, NN, HF, 0);
    elr_kernel<<<warp_blocks, 256>>>(al1, ar1);
    edge_softmax_kernel<<<warp_blocks, 256>>>();
    aggregate_kernel<<<NN, 128>>>(b1);
    actmean_kernel<<<(NN*HIDN + TB - 1)/TB, TB>>>();

    // ---- GAT layer 2 ----
    sgemm128_kernel<<<g_gat, 256>>>(px, W2, nullptr, ph, NN, HF, 0);
    elr_kernel<<<warp_blocks, 256>>>(al2, ar2);
    edge_softmax_kernel<<<warp_blocks, 256>>>();
    aggregate_kernel<<<NN, 128>>>(b2);
    actmean_kernel<<<(NN*HIDN + TB - 1)/TB, TB>>>();

    // ---- MLP head ----
    sgemm128_kernel<<<g_mlp, 256>>>(px, lw1, lb1, py, NN, HIDN, 1);
    sgemm128_kernel<<<g_mlp, 256>>>(py, lw2, lb2, px, NN, HIDN, 1);
    sgemm128_kernel<<<g_mlp, 256>>>(px, lw3, lb3, py, NN, HIDN, 1);
    sgemm128_kernel<<<g_mlp, 256>>>(py, lw4, lb4, px, NN, HIDN, 1);
    classifier_kernel<<<(NN + 7)/8, 256>>>(lw5, lb5, out);
}

// round 3
// speedup vs baseline: 1.6956x; 1.2863x over previous
#include <cuda_runtime.h>

#define NN 50000
#define EE 800000
#define HH 3
#define INF 128
#define HIDN 128
#define HF (HH*HIDN)   // 384
#define NCLS 6

typedef unsigned long long u64t;

// ---------------- scratch (device globals; no allocation allowed) --------
__device__ float g_h[NN*HF];       // post-GEMM per-head features
__device__ float g_x[NN*HIDN];     // layer input / MLP ping
__device__ float g_y[NN*HIDN];     // MLP pong
__device__ float g_el[NN*HH];
__device__ float g_er[NN*HH];
__device__ float g_alpha[3*EE];    // planar: [h][csr_pos]
__device__ int   g_srcs[EE];       // src node id in CSR order
__device__ int   g_deg[NN];
__device__ int   g_rowptr[NN+1];
__device__ int   g_wptr[NN];

// ---------------- f32x2 helpers ------------------------------------------
__device__ __forceinline__ u64t pack2(float lo, float hi) {
    u64t r;
    asm("mov.b64 %0, {%1, %2};" : "=l"(r) : "f"(lo), "f"(hi));
    return r;
}
__device__ __forceinline__ void unpack2(u64t v, float& lo, float& hi) {
    asm("mov.b64 {%0, %1}, %2;" : "=f"(lo), "=f"(hi) : "l"(v));
}
__device__ __forceinline__ void ffma2(u64t& d, u64t a, u64t b) {
    asm("fma.rn.f32x2 %0, %1, %2, %0;" : "+l"(d) : "l"(a), "l"(b));
}

// ---------------- CSR build ----------------------------------------------
__global__ void zero_deg_kernel() {
    int i = blockIdx.x*blockDim.x + threadIdx.x;
    if (i < NN) g_deg[i] = 0;
}

__global__ void hist_kernel(const int* __restrict__ dst) {
    int i = blockIdx.x*blockDim.x + threadIdx.x;
    if (i < EE) atomicAdd(&g_deg[dst[i]], 1);
}

__global__ void scan_kernel() {
    __shared__ int sh[1024];
    int t = threadIdx.x;
    const int ITEMS = (NN + 1023) / 1024;   // 49
    int base = t * ITEMS;
    int s = 0;
    for (int i = 0; i < ITEMS; i++) {
        int idx = base + i;
        if (idx < NN) s += g_deg[idx];
    }
    sh[t] = s;
    __syncthreads();
    for (int off = 1; off < 1024; off <<= 1) {
        int v = (t >= off) ? sh[t - off] : 0;
        __syncthreads();
        sh[t] += v;
        __syncthreads();
    }
    int run = sh[t] - s;   // exclusive prefix
    for (int i = 0; i < ITEMS; i++) {
        int idx = base + i;
        if (idx < NN) {
            g_rowptr[idx] = run;
            g_wptr[idx]   = run;
            run += g_deg[idx];
        }
    }
    if (t == 0) g_rowptr[NN] = EE;
}

__global__ void scatter_kernel(const int* __restrict__ src, const int* __restrict__ dst) {
    int i = blockIdx.x*blockDim.x + threadIdx.x;
    if (i < EE) {
        int d = dst[i];
        int p = atomicAdd(&g_wptr[d], 1);
        g_srcs[p] = src[i];
    }
}

// ---------------- SGEMM 128x128 tile, f32x2 packed FMA -------------------
// C(MxNcols) = A(Mx128) @ B(128xNcols) [+bias][+leaky 0.01]; Ncols%128==0.
// If al != nullptr: per-row attention dots for head hh=blockIdx.x are
// reduced in the epilogue and written to g_el/g_er (GAT path: bias=null,
// act=0, Ncols=384 so one col-block == one head).
__global__ __launch_bounds__(256, 2)
void sgemm128_kernel(const float* __restrict__ A, const float* __restrict__ B,
                     const float* __restrict__ bias, float* __restrict__ C,
                     int M, int Ncols, int act,
                     const float* __restrict__ al, const float* __restrict__ ar)
{
    __shared__ float As[2][16][128];   // k-major (transposed)
    __shared__ float Bs[2][16][128];
    int tid = threadIdx.x;
    int tx = tid & 15, ty = tid >> 4;
    int row0 = blockIdx.y * 128, col0 = blockIdx.x * 128;

    u64t acc2[4][8];                   // [row-pair][col], lanes = 2 rows
    #pragma unroll
    for (int i = 0; i < 4; i++)
        #pragma unroll
        for (int j = 0; j < 8; j++) acc2[i][j] = 0ull;

    const float4 z4 = make_float4(0.f, 0.f, 0.f, 0.f);

    // prologue: load k-tile 0 into buffer 0
    #pragma unroll
    for (int i = 0; i < 2; i++) {
        int q = tid + i * 256;
        int r = q >> 2, c4 = q & 3;
        int gr = row0 + r;
        float4 av = (gr < M) ? *(const float4*)&A[gr*128 + c4*4] : z4;
        As[0][c4*4+0][r] = av.x;
        As[0][c4*4+1][r] = av.y;
        As[0][c4*4+2][r] = av.z;
        As[0][c4*4+3][r] = av.w;
        int kr = q >> 5, n4 = q & 31;
        *(float4*)&Bs[0][kr][n4*4] = *(const float4*)&B[kr*Ncols + col0 + n4*4];
    }
    __syncthreads();

    #pragma unroll
    for (int kt = 0; kt < 8; kt++) {
        int buf = kt & 1;
        float4 a_pref[2], b_pref[2];
        if (kt < 7) {
            int k0 = (kt + 1) * 16;
            #pragma unroll
            for (int i = 0; i < 2; i++) {
                int q = tid + i * 256;
                int r = q >> 2, c4 = q & 3;
                int gr = row0 + r;
                a_pref[i] = (gr < M) ? *(const float4*)&A[gr*128 + k0 + c4*4] : z4;
                int kr = q >> 5, n4 = q & 31;
                b_pref[i] = *(const float4*)&B[(k0 + kr)*Ncols + col0 + n4*4];
            }
        }
        #pragma unroll
        for (int k = 0; k < 16; k++) {
            // A row-pairs: 4 x 64-bit shared loads (rows 2i2, 2i2+1)
            const u64t* ap = (const u64t*)&As[buf][k][ty*8];
            u64t a2[4];
            #pragma unroll
            for (int i = 0; i < 4; i++) a2[i] = ap[i];
            // B: 8 scalars, broadcast-packed
            float4 b0 = *(const float4*)&Bs[buf][k][tx*8];
            float4 b1 = *(const float4*)&Bs[buf][k][tx*8 + 4];
            float bf[8] = {b0.x,b0.y,b0.z,b0.w,b1.x,b1.y,b1.z,b1.w};
            u64t bb[8];
            #pragma unroll
            for (int j = 0; j < 8; j++) bb[j] = pack2(bf[j], bf[j]);
            #pragma unroll
            for (int i = 0; i < 4; i++)
                #pragma unroll
                for (int j = 0; j < 8; j++)
                    ffma2(acc2[i][j], a2[i], bb[j]);
        }
        if (kt < 7) {
            int nbuf = buf ^ 1;
            #pragma unroll
            for (int i = 0; i < 2; i++) {
                int q = tid + i * 256;
                int r = q >> 2, c4 = q & 3;
                As[nbuf][c4*4+0][r] = a_pref[i].x;
                As[nbuf][c4*4+1][r] = a_pref[i].y;
                As[nbuf][c4*4+2][r] = a_pref[i].z;
                As[nbuf][c4*4+3][r] = a_pref[i].w;
                int kr = q >> 5, n4 = q & 31;
                *(float4*)&Bs[nbuf][kr][n4*4] = b_pref[i];
            }
            __syncthreads();
        }
    }

    // epilogue
    float bbia[8];
    #pragma unroll
    for (int j = 0; j < 8; j++)
        bbia[j] = bias ? bias[col0 + tx*8 + j] : 0.f;

    int hh = blockIdx.x;                // head id when Ncols==HF
    float als[8], ars[8];
    if (al) {
        #pragma unroll
        for (int j = 0; j < 8; j++) {
            als[j] = __ldg(&al[hh*HIDN + tx*8 + j]);
            ars[j] = __ldg(&ar[hh*HIDN + tx*8 + j]);
        }
    }

    #pragma unroll
    for (int i2 = 0; i2 < 4; i2++) {
        float vlo[8], vhi[8];
        #pragma unroll
        for (int j = 0; j < 8; j++) unpack2(acc2[i2][j], vlo[j], vhi[j]);
        #pragma unroll
        for (int half = 0; half < 2; half++) {
            float* v = half ? vhi : vlo;
            int r = row0 + ty*8 + i2*2 + half;
            float w[8];
            #pragma unroll
            for (int j = 0; j < 8; j++) {
                float t = v[j] + bbia[j];
                w[j] = act ? (t > 0.f ? t : 0.01f*t) : t;
            }
            if (r < M) {
                *(float4*)&C[r*Ncols + col0 + tx*8]     = make_float4(w[0],w[1],w[2],w[3]);
                *(float4*)&C[r*Ncols + col0 + tx*8 + 4] = make_float4(w[4],w[5],w[6],w[7]);
            }
            if (al) {
                float pl = 0.f, pr = 0.f;
                #pragma unroll
                for (int j = 0; j < 8; j++) { pl += v[j]*als[j]; pr += v[j]*ars[j]; }
                #pragma unroll
                for (int o = 8; o; o >>= 1) {
                    pl += __shfl_xor_sync(0xffffffffu, pl, o);
                    pr += __shfl_xor_sync(0xffffffffu, pr, o);
                }
                if (tx == 0 && r < M) {
                    g_el[r*HH + hh] = pl;
                    g_er[r*HH + hh] = pr;
                }
            }
        }
    }
}

// ---------------- fused edge logits + softmax, warp per (dst,head) -------
__global__ void edge_softmax_kernel()
{
    int gw   = (blockIdx.x*blockDim.x + threadIdx.x) >> 5;
    int lane = threadIdx.x & 31;
    if (gw >= NN*HH) return;
    int n = gw / HH, hh = gw % HH;
    int beg = g_rowptr[n], end = g_rowptr[n+1];
    if (beg == end) return;
    float er_n = g_er[n*HH + hh];
    float* ap = &g_alpha[hh*EE];
    float mx = -1e30f;
    for (int j = beg + lane; j < end; j += 32) {
        int s = g_srcs[j];
        float v = g_el[s*HH + hh] + er_n;
        v = v > 0.f ? v : 0.2f*v;
        ap[j] = v;
        mx = fmaxf(mx, v);
    }
    #pragma unroll
    for (int o = 16; o; o >>= 1) mx = fmaxf(mx, __shfl_xor_sync(0xffffffffu, mx, o));
    float s = 0.f;
    for (int j = beg + lane; j < end; j += 32) {
        float e = expf(ap[j] - mx);
        ap[j] = e;
        s += e;
    }
    #pragma unroll
    for (int o = 16; o; o >>= 1) s += __shfl_xor_sync(0xffffffffu, s, o);
    float inv = 1.f / (s + 1e-9f);
    for (int j = beg + lane; j < end; j += 32)
        ap[j] *= inv;
}

// -------- aggregation fused with +bias, leaky(0.01), head-mean -> g_x ----
__global__ void aggregate_kernel(const float* __restrict__ bias)
{
    int n = blockIdx.x;
    int t = threadIdx.x;     // 128 threads, one feature per head
    int beg = g_rowptr[n], end = g_rowptr[n+1];
    float a0 = 0.f, a1 = 0.f, a2 = 0.f;
    for (int j = beg; j < end; j++) {
        int s = g_srcs[j];
        float w0 = __ldg(&g_alpha[j]);
        float w1 = __ldg(&g_alpha[EE + j]);
        float w2 = __ldg(&g_alpha[2*EE + j]);
        const float* hr = &g_h[s*HF];
        a0 += w0 * __ldg(&hr[t]);
        a1 += w1 * __ldg(&hr[HIDN + t]);
        a2 += w2 * __ldg(&hr[2*HIDN + t]);
    }
    a0 += bias[t];
    a1 += bias[HIDN + t];
    a2 += bias[2*HIDN + t];
    a0 = a0 > 0.f ? a0 : 0.01f*a0;
    a1 = a1 > 0.f ? a1 : 0.01f*a1;
    a2 = a2 > 0.f ? a2 : 0.01f*a2;
    g_x[n*HIDN + t] = (a0 + a1 + a2) * (1.f/3.f);
}

// ---------------- classifier: (N,128)@(128,6)+b, warp per node -----------
__global__ void classifier_kernel(const float* __restrict__ lw5, const float* __restrict__ lb5,
                                  float* __restrict__ out)
{
    int gw   = (blockIdx.x*blockDim.x + threadIdx.x) >> 5;
    int lane = threadIdx.x & 31;
    if (gw >= NN) return;
    const float* xr = &g_x[gw*HIDN];
    float acc[NCLS] = {};
    #pragma unroll
    for (int k = lane; k < HIDN; k += 32) {
        float xv = xr[k];
        #pragma unroll
        for (int c = 0; c < NCLS; c++) acc[c] += xv * __ldg(&lw5[k*NCLS + c]);
    }
    #pragma unroll
    for (int c = 0; c < NCLS; c++)
        #pragma unroll
        for (int o = 16; o; o >>= 1) acc[c] += __shfl_xor_sync(0xffffffffu, acc[c], o);
    if (lane == 0) {
        #pragma unroll
        for (int c = 0; c < NCLS; c++) out[gw*NCLS + c] = acc[c] + lb5[c];
    }
}

// -------------------------------------------------------------------------
extern "C" void kernel_launch(void* const* d_in, const int* in_sizes, int n_in,
                              void* d_out, int out_size)
{
    const float* in_feat = (const float*)d_in[0];
    const int*   src     = (const int*)  d_in[1];
    const int*   dst     = (const int*)  d_in[2];
    const float* W1  = (const float*)d_in[3];
    const float* al1 = (const float*)d_in[4];
    const float* ar1 = (const float*)d_in[5];
    const float* b1  = (const float*)d_in[6];
    const float* W2  = (const float*)d_in[7];
    const float* al2 = (const float*)d_in[8];
    const float* ar2 = (const float*)d_in[9];
    const float* b2  = (const float*)d_in[10];
    const float* lw1 = (const float*)d_in[11];
    const float* lb1 = (const float*)d_in[12];
    const float* lw2 = (const float*)d_in[13];
    const float* lb2 = (const float*)d_in[14];
    const float* lw3 = (const float*)d_in[15];
    const float* lb3 = (const float*)d_in[16];
    const float* lw4 = (const float*)d_in[17];
    const float* lb4 = (const float*)d_in[18];
    const float* lw5 = (const float*)d_in[19];
    const float* lb5 = (const float*)d_in[20];
    float* out = (float*)d_out;

    float *ph, *px, *py;
    cudaGetSymbolAddress((void**)&ph, g_h);
    cudaGetSymbolAddress((void**)&px, g_x);
    cudaGetSymbolAddress((void**)&py, g_y);

    const int TB = 256;
    int warp_blocks = (NN*HH + 7) / 8;   // 8 warps per 256-thread block

    // CSR build (shared by both layers)
    zero_deg_kernel<<<(NN + TB - 1)/TB, TB>>>();
    hist_kernel<<<(EE + TB - 1)/TB, TB>>>(dst);
    scan_kernel<<<1, 1024>>>();
    scatter_kernel<<<(EE + TB - 1)/TB, TB>>>(src, dst);

    dim3 g_gat(HF/128, (NN + 127)/128);
    dim3 g_mlp(HIDN/128, (NN + 127)/128);

    // ---- GAT layer 1 ----
    sgemm128_kernel<<<g_gat, 256>>>(in_feat, W1, nullptr, ph, NN, HF, 0, al1, ar1);
    edge_softmax_kernel<<<warp_blocks, 256>>>();
    aggregate_kernel<<<NN, 128>>>(b1);

    // ---- GAT layer 2 ----
    sgemm128_kernel<<<g_gat, 256>>>(px, W2, nullptr, ph, NN, HF, 0, al2, ar2);
    edge_softmax_kernel<<<warp_blocks, 256>>>();
    aggregate_kernel<<<NN, 128>>>(b2);

    // ---- MLP head ----
    sgemm128_kernel<<<g_mlp, 256>>>(px, lw1, lb1, py, NN, HIDN, 1, nullptr, nullptr);
    sgemm128_kernel<<<g_mlp, 256>>>(py, lw2, lb2, px, NN, HIDN, 1, nullptr, nullptr);
    sgemm128_kernel<<<g_mlp, 256>>>(px, lw3, lb3, py, NN, HIDN, 1, nullptr, nullptr);
    sgemm128_kernel<<<g_mlp, 256>>>(py, lw4, lb4, px, NN, HIDN, 1, nullptr, nullptr);
    classifier_kernel<<<(NN + 7)/8, 256>>>(lw5, lb5, out);
}

// round 4
// speedup vs baseline: 1.7493x; 1.0317x over previous
#include <cuda_runtime.h>
#include <cstdint>

#define NN 50000
#define EE 800000
#define HH 3
#define HIDN 128
#define HF (HH*HIDN)   // 384
#define NCLS 6

#define BM 64
#define BN 128
#define BK 16
#define ASTR 20        // A smem row stride (words), conflict-free frag loads
#define BSTR 136       // B smem row stride (words)

// ---------------- scratch (device globals; no allocation allowed) --------
__device__ float g_h[NN*HF];       // post-GEMM per-head features
__device__ float g_x[NN*HIDN];     // layer input / MLP ping
__device__ float g_y[NN*HIDN];     // MLP pong
__device__ float g_el[NN*HH];
__device__ float g_er[NN*HH];
__device__ float g_dnm[NN*HH];     // 1/denominator per (node, head)
__device__ float g_alpha[3*EE];    // planar: [h][csr_pos], holds exp values
__device__ int   g_srcs[EE];       // src node id in CSR order
__device__ int   g_deg[NN];
__device__ int   g_rowptr[NN+1];
__device__ int   g_wptr[NN];

// ---------------- helpers -------------------------------------------------
__device__ __forceinline__ uint32_t cvt_tf32(float f) {
    uint32_t r;
    asm("cvt.rna.tf32.f32 %0, %1;" : "=r"(r) : "f"(f));
    return r;
}
__device__ __forceinline__ void mma8(float* c, const uint32_t* a, uint32_t b0, uint32_t b1) {
    asm("mma.sync.aligned.m16n8k8.row.col.f32.tf32.tf32.f32 "
        "{%0,%1,%2,%3}, {%4,%5,%6,%7}, {%8,%9}, {%0,%1,%2,%3};"
        : "+f"(c[0]), "+f"(c[1]), "+f"(c[2]), "+f"(c[3])
        : "r"(a[0]), "r"(a[1]), "r"(a[2]), "r"(a[3]), "r"(b0), "r"(b1));
}

// ---------------- CSR build ----------------------------------------------
__global__ void zero_deg_kernel() {
    int i = blockIdx.x*blockDim.x + threadIdx.x;
    if (i < NN) g_deg[i] = 0;
}

__global__ void hist_kernel(const int* __restrict__ dst) {
    int i = blockIdx.x*blockDim.x + threadIdx.x;
    if (i < EE) atomicAdd(&g_deg[dst[i]], 1);
}

__global__ void scan_kernel() {
    __shared__ int sh[1024];
    int t = threadIdx.x;
    const int ITEMS = (NN + 1023) / 1024;   // 49
    int base = t * ITEMS;
    int s = 0;
    for (int i = 0; i < ITEMS; i++) {
        int idx = base + i;
        if (idx < NN) s += g_deg[idx];
    }
    sh[t] = s;
    __syncthreads();
    for (int off = 1; off < 1024; off <<= 1) {
        int v = (t >= off) ? sh[t - off] : 0;
        __syncthreads();
        sh[t] += v;
        __syncthreads();
    }
    int run = sh[t] - s;   // exclusive prefix
    for (int i = 0; i < ITEMS; i++) {
        int idx = base + i;
        if (idx < NN) {
            g_rowptr[idx] = run;
            g_wptr[idx]   = run;
            run += g_deg[idx];
        }
    }
    if (t == 0) g_rowptr[NN] = EE;
}

__global__ void scatter_kernel(const int* __restrict__ src, const int* __restrict__ dst) {
    int i = blockIdx.x*blockDim.x + threadIdx.x;
    if (i < EE) {
        int d = dst[i];
        int p = atomicAdd(&g_wptr[d], 1);
        g_srcs[p] = src[i];
    }
}

// ------------- tf32x3 tensor-core GEMM: C = A(Mx128)@B(128xN) ------------
// [+bias][+leaky 0.01]; Ncols % 128 == 0, K fixed at 128.
// If al != nullptr: attention dots for head hh=blockIdx.x reduced in the
// epilogue into g_el/g_er (GAT path: Ncols=384, one col-block == one head).
__global__ __launch_bounds__(256, 2)
void tf32gemm_kernel(const float* __restrict__ A, const float* __restrict__ B,
                     const float* __restrict__ bias, float* __restrict__ C,
                     int M, int Ncols, int act,
                     const float* __restrict__ al, const float* __restrict__ ar)
{
    __shared__ uint32_t As[2][BM*ASTR];   // [hi/lo plane][m*ASTR + k]
    __shared__ uint32_t Bs[2][BK*BSTR];   // [hi/lo plane][k*BSTR + n]
    __shared__ float sEl[4][BM], sEr[4][BM];

    int tid  = threadIdx.x;
    int lane = tid & 31, warp = tid >> 5;
    int wm = warp >> 2, wn = warp & 3;        // 2 x 4 warp grid
    int m0 = blockIdx.y * BM, col0 = blockIdx.x * BN;

    float acc[2][4][4];
    #pragma unroll
    for (int i = 0; i < 2; i++)
        #pragma unroll
        for (int j = 0; j < 4; j++)
            #pragma unroll
            for (int q = 0; q < 4; q++) acc[i][j][q] = 0.f;

    // load index maps
    int arow = tid >> 2;        // 0..63
    int aj   = tid & 3;         // k-quad
    int bn4  = tid & 31;        // n-quad
    int bk   = tid >> 5;        // 0..7

    const float4 z4 = make_float4(0.f,0.f,0.f,0.f);
    float4 aL, bL0, bL1;
    {   // prefetch chunk 0
        int gr = m0 + arow;
        aL  = (gr < M) ? *(const float4*)&A[gr*128 + aj*4] : z4;
        bL0 = *(const float4*)&B[bk*Ncols + col0 + bn4*4];
        bL1 = *(const float4*)&B[(bk+8)*Ncols + col0 + bn4*4];
    }

    #pragma unroll 1
    for (int ch = 0; ch < 8; ch++) {
        if (ch) __syncthreads();          // previous mma reads done
        {   // split + store A
            float v[4] = {aL.x, aL.y, aL.z, aL.w};
            uint32_t h4[4], l4[4];
            #pragma unroll
            for (int e = 0; e < 4; e++) {
                h4[e] = cvt_tf32(v[e]);
                l4[e] = cvt_tf32(v[e] - __uint_as_float(h4[e]));
            }
            *(uint4*)&As[0][arow*ASTR + aj*4] = make_uint4(h4[0],h4[1],h4[2],h4[3]);
            *(uint4*)&As[1][arow*ASTR + aj*4] = make_uint4(l4[0],l4[1],l4[2],l4[3]);
            // split + store B (two rows)
            float w0[4] = {bL0.x, bL0.y, bL0.z, bL0.w};
            float w1[4] = {bL1.x, bL1.y, bL1.z, bL1.w};
            uint32_t bh0[4], blo0[4], bh1[4], blo1[4];
            #pragma unroll
            for (int e = 0; e < 4; e++) {
                bh0[e] = cvt_tf32(w0[e]);
                blo0[e] = cvt_tf32(w0[e] - __uint_as_float(bh0[e]));
                bh1[e] = cvt_tf32(w1[e]);
                blo1[e] = cvt_tf32(w1[e] - __uint_as_float(bh1[e]));
            }
            *(uint4*)&Bs[0][bk*BSTR + bn4*4]     = make_uint4(bh0[0],bh0[1],bh0[2],bh0[3]);
            *(uint4*)&Bs[1][bk*BSTR + bn4*4]     = make_uint4(blo0[0],blo0[1],blo0[2],blo0[3]);
            *(uint4*)&Bs[0][(bk+8)*BSTR + bn4*4] = make_uint4(bh1[0],bh1[1],bh1[2],bh1[3]);
            *(uint4*)&Bs[1][(bk+8)*BSTR + bn4*4] = make_uint4(blo1[0],blo1[1],blo1[2],blo1[3]);
        }
        __syncthreads();
        if (ch < 7) {   // prefetch next chunk (overlaps mma below)
            int k0 = (ch + 1) * BK;
            int gr = m0 + arow;
            aL  = (gr < M) ? *(const float4*)&A[gr*128 + k0 + aj*4] : z4;
            bL0 = *(const float4*)&B[(k0 + bk)*Ncols + col0 + bn4*4];
            bL1 = *(const float4*)&B[(k0 + bk + 8)*Ncols + col0 + bn4*4];
        }
        #pragma unroll
        for (int ks = 0; ks < 2; ks++) {
            int kk = ks * 8;
            uint32_t ah[2][4], alo[2][4];
            #pragma unroll
            for (int mt = 0; mt < 2; mt++) {
                int mb = wm*32 + mt*16 + (lane >> 2);
                int kb = kk + (lane & 3);
                ah[mt][0]  = As[0][mb*ASTR + kb];
                ah[mt][1]  = As[0][(mb+8)*ASTR + kb];
                ah[mt][2]  = As[0][mb*ASTR + kb + 4];
                ah[mt][3]  = As[0][(mb+8)*ASTR + kb + 4];
                alo[mt][0] = As[1][mb*ASTR + kb];
                alo[mt][1] = As[1][(mb+8)*ASTR + kb];
                alo[mt][2] = As[1][mb*ASTR + kb + 4];
                alo[mt][3] = As[1][(mb+8)*ASTR + kb + 4];
            }
            #pragma unroll
            for (int nt = 0; nt < 4; nt++) {
                int nb = wn*32 + nt*8 + (lane >> 2);
                int kb = kk + (lane & 3);
                uint32_t bh0 = Bs[0][kb*BSTR + nb];
                uint32_t bh1 = Bs[0][(kb+4)*BSTR + nb];
                uint32_t bl0 = Bs[1][kb*BSTR + nb];
                uint32_t bl1 = Bs[1][(kb+4)*BSTR + nb];
                #pragma unroll
                for (int mt = 0; mt < 2; mt++) {
                    mma8(acc[mt][nt], ah[mt],  bh0, bh1);
                    mma8(acc[mt][nt], ah[mt],  bl0, bl1);
                    mma8(acc[mt][nt], alo[mt], bh0, bh1);
                }
            }
        }
    }

    // ---------------- epilogue: store C ----------------------------------
    #pragma unroll
    for (int mt = 0; mt < 2; mt++) {
        #pragma unroll
        for (int half = 0; half < 2; half++) {
            int r = m0 + wm*32 + mt*16 + (lane >> 2) + half*8;
            if (r >= M) continue;
            #pragma unroll
            for (int nt = 0; nt < 4; nt++) {
                int c = col0 + wn*32 + nt*8 + 2*(lane & 3);
                float v0 = acc[mt][nt][half*2 + 0];
                float v1 = acc[mt][nt][half*2 + 1];
                if (bias) { v0 += bias[c]; v1 += bias[c+1]; }
                if (act)  { v0 = v0 > 0.f ? v0 : 0.01f*v0;
                            v1 = v1 > 0.f ? v1 : 0.01f*v1; }
                *(float2*)&C[r*Ncols + c] = make_float2(v0, v1);
            }
        }
    }

    // ---------------- fused attention dots (GAT path) --------------------
    if (al) {
        int hh = blockIdx.x;
        float alv[4][2], arv[4][2];
        #pragma unroll
        for (int nt = 0; nt < 4; nt++)
            #pragma unroll
            for (int j = 0; j < 2; j++) {
                int c = wn*32 + nt*8 + 2*(lane & 3) + j;
                alv[nt][j] = __ldg(&al[hh*HIDN + c]);
                arv[nt][j] = __ldg(&ar[hh*HIDN + c]);
            }
        #pragma unroll
        for (int mt = 0; mt < 2; mt++) {
            #pragma unroll
            for (int half = 0; half < 2; half++) {
                float pl = 0.f, pr = 0.f;
                #pragma unroll
                for (int nt = 0; nt < 4; nt++)
                    #pragma unroll
                    for (int j = 0; j < 2; j++) {
                        float v = acc[mt][nt][half*2 + j];
                        pl += v * alv[nt][j];
                        pr += v * arv[nt][j];
                    }
                pl += __shfl_xor_sync(0xffffffffu, pl, 1);
                pl += __shfl_xor_sync(0xffffffffu, pl, 2);
                pr += __shfl_xor_sync(0xffffffffu, pr, 1);
                pr += __shfl_xor_sync(0xffffffffu, pr, 2);
                if ((lane & 3) == 0) {
                    int rl = wm*32 + mt*16 + (lane >> 2) + half*8;
                    sEl[wn][rl] = pl;
                    sEr[wn][rl] = pr;
                }
            }
        }
        __syncthreads();
        if (tid < BM) {
            int r = m0 + tid;
            if (r < M) {
                g_el[r*HH + hh] = sEl[0][tid] + sEl[1][tid] + sEl[2][tid] + sEl[3][tid];
                g_er[r*HH + hh] = sEr[0][tid] + sEr[1][tid] + sEr[2][tid] + sEr[3][tid];
            }
        }
    }
}

// ---------------- fused edge logits + softmax, warp per (dst,head) -------
// Stores exp values in g_alpha and 1/denominator in g_dnm (no pass-3 scale).
__global__ void edge_softmax_kernel()
{
    int gw   = (blockIdx.x*blockDim.x + threadIdx.x) >> 5;
    int lane = threadIdx.x & 31;
    if (gw >= NN*HH) return;
    int n = gw / HH, hh = gw % HH;
    int beg = g_rowptr[n], end = g_rowptr[n+1];
    if (beg == end) return;
    float er_n = g_er[n*HH + hh];
    float* ap = &g_alpha[hh*EE];
    float mx = -1e30f;
    for (int j = beg + lane; j < end; j += 32) {
        int s = g_srcs[j];
        float v = g_el[s*HH + hh] + er_n;
        v = v > 0.f ? v : 0.2f*v;
        ap[j] = v;
        mx = fmaxf(mx, v);
    }
    #pragma unroll
    for (int o = 16; o; o >>= 1) mx = fmaxf(mx, __shfl_xor_sync(0xffffffffu, mx, o));
    float s = 0.f;
    for (int j = beg + lane; j < end; j += 32) {
        float e = expf(ap[j] - mx);
        ap[j] = e;
        s += e;
    }
    #pragma unroll
    for (int o = 16; o; o >>= 1) s += __shfl_xor_sync(0xffffffffu, s, o);
    if (lane == 0) g_dnm[n*HH + hh] = 1.f / (s + 1e-9f);
}

// ------ aggregation + inv-denom + bias + leaky(0.01) + head-mean -> g_x --
__global__ void aggregate_kernel(const float* __restrict__ bias)
{
    int n = blockIdx.x;
    int t = threadIdx.x;     // 128 threads, one feature per head
    int beg = g_rowptr[n], end = g_rowptr[n+1];
    float a0 = 0.f, a1 = 0.f, a2 = 0.f;
    for (int j = beg; j < end; j++) {
        int s = g_srcs[j];
        float w0 = __ldg(&g_alpha[j]);
        float w1 = __ldg(&g_alpha[EE + j]);
        float w2 = __ldg(&g_alpha[2*EE + j]);
        const float* hr = &g_h[s*HF];
        a0 += w0 * __ldg(&hr[t]);
        a1 += w1 * __ldg(&hr[HIDN + t]);
        a2 += w2 * __ldg(&hr[2*HIDN + t]);
    }
    a0 = a0 * g_dnm[n*HH + 0] + bias[t];
    a1 = a1 * g_dnm[n*HH + 1] + bias[HIDN + t];
    a2 = a2 * g_dnm[n*HH + 2] + bias[2*HIDN + t];
    a0 = a0 > 0.f ? a0 : 0.01f*a0;
    a1 = a1 > 0.f ? a1 : 0.01f*a1;
    a2 = a2 > 0.f ? a2 : 0.01f*a2;
    g_x[n*HIDN + t] = (a0 + a1 + a2) * (1.f/3.f);
}

// ---------------- classifier: (N,128)@(128,6)+b, warp per node -----------
__global__ void classifier_kernel(const float* __restrict__ lw5, const float* __restrict__ lb5,
                                  float* __restrict__ out)
{
    int gw   = (blockIdx.x*blockDim.x + threadIdx.x) >> 5;
    int lane = threadIdx.x & 31;
    if (gw >= NN) return;
    const float* xr = &g_x[gw*HIDN];
    float acc[NCLS] = {};
    #pragma unroll
    for (int k = lane; k < HIDN; k += 32) {
        float xv = xr[k];
        #pragma unroll
        for (int c = 0; c < NCLS; c++) acc[c] += xv * __ldg(&lw5[k*NCLS + c]);
    }
    #pragma unroll
    for (int c = 0; c < NCLS; c++)
        #pragma unroll
        for (int o = 16; o; o >>= 1) acc[c] += __shfl_xor_sync(0xffffffffu, acc[c], o);
    if (lane == 0) {
        #pragma unroll
        for (int c = 0; c < NCLS; c++) out[gw*NCLS + c] = acc[c] + lb5[c];
    }
}

// -------------------------------------------------------------------------
extern "C" void kernel_launch(void* const* d_in, const int* in_sizes, int n_in,
                              void* d_out, int out_size)
{
    const float* in_feat = (const float*)d_in[0];
    const int*   src     = (const int*)  d_in[1];
    const int*   dst     = (const int*)  d_in[2];
    const float* W1  = (const float*)d_in[3];
    const float* al1 = (const float*)d_in[4];
    const float* ar1 = (const float*)d_in[5];
    const float* b1  = (const float*)d_in[6];
    const float* W2  = (const float*)d_in[7];
    const float* al2 = (const float*)d_in[8];
    const float* ar2 = (const float*)d_in[9];
    const float* b2  = (const float*)d_in[10];
    const float* lw1 = (const float*)d_in[11];
    const float* lb1 = (const float*)d_in[12];
    const float* lw2 = (const float*)d_in[13];
    const float* lb2 = (const float*)d_in[14];
    const float* lw3 = (const float*)d_in[15];
    const float* lb3 = (const float*)d_in[16];
    const float* lw4 = (const float*)d_in[17];
    const float* lb4 = (const float*)d_in[18];
    const float* lw5 = (const float*)d_in[19];
    const float* lb5 = (const float*)d_in[20];
    float* out = (float*)d_out;

    float *ph, *px, *py;
    cudaGetSymbolAddress((void**)&ph, g_h);
    cudaGetSymbolAddress((void**)&px, g_x);
    cudaGetSymbolAddress((void**)&py, g_y);

    const int TB = 256;
    int warp_blocks = (NN*HH + 7) / 8;   // 8 warps per 256-thread block

    // CSR build (shared by both layers)
    zero_deg_kernel<<<(NN + TB - 1)/TB, TB>>>();
    hist_kernel<<<(EE + TB - 1)/TB, TB>>>(dst);
    scan_kernel<<<1, 1024>>>();
    scatter_kernel<<<(EE + TB - 1)/TB, TB>>>(src, dst);

    dim3 g_gat(HF/BN, (NN + BM - 1)/BM);     // (3, 782)
    dim3 g_mlp(HIDN/BN, (NN + BM - 1)/BM);   // (1, 782)

    // ---- GAT layer 1 ----
    tf32gemm_kernel<<<g_gat, 256>>>(in_feat, W1, nullptr, ph, NN, HF, 0, al1, ar1);
    edge_softmax_kernel<<<warp_blocks, 256>>>();
    aggregate_kernel<<<NN, 128>>>(b1);

    // ---- GAT layer 2 ----
    tf32gemm_kernel<<<g_gat, 256>>>(px, W2, nullptr, ph, NN, HF, 0, al2, ar2);
    edge_softmax_kernel<<<warp_blocks, 256>>>();
    aggregate_kernel<<<NN, 128>>>(b2);

    // ---- MLP head ----
    tf32gemm_kernel<<<g_mlp, 256>>>(px, lw1, lb1, py, NN, HIDN, 1, nullptr, nullptr);
    tf32gemm_kernel<<<g_mlp, 256>>>(py, lw2, lb2, px, NN, HIDN, 1, nullptr, nullptr);
    tf32gemm_kernel<<<g_mlp, 256>>>(px, lw3, lb3, py, NN, HIDN, 1, nullptr, nullptr);
    tf32gemm_kernel<<<g_mlp, 256>>>(py, lw4, lb4, px, NN, HIDN, 1, nullptr, nullptr);
    classifier_kernel<<<(NN + 7)/8, 256>>>(lw5, lb5, out);
}

// round 5
// speedup vs baseline: 1.9117x; 1.0929x over previous
#include <cuda_runtime.h>
#include <cstdint>

#define NN 50000
#define EE 800000
#define HH 3
#define HIDN 128
#define HF (HH*HIDN)   // 384
#define NCLS 6

#define BM 128
#define BN 128
#define BK 16
// fragment-layout block sizes (words), with skew for bank-conflict freedom
#define A_BLK 132      // 32 lanes * 4 regs + 4 skew
#define A_PL  2112     // 16 blocks * 132
#define B_NT  66       // 32 lanes * 2 regs + 2 skew
#define B_KS  532      // 8 nt * 66 + 4 skew
#define B_PL  2128     // 4 ks-blocks * 532

// ---------------- scratch (device globals; no allocation allowed) --------
__device__ float g_h[NN*HF];       // post-GEMM per-head features
__device__ float g_x[NN*HIDN];     // layer input / MLP ping
__device__ float g_y[NN*HIDN];     // MLP pong
__device__ float g_el[NN*HH];
__device__ float g_er[NN*HH];
__device__ float g_dnm[NN*HH];     // 1/denominator per (node, head)
__device__ float g_alpha[3*EE];    // planar: [h][csr_pos], exp values
__device__ int   g_srcs[EE];       // src node id in CSR order
__device__ int   g_deg[NN];
__device__ int   g_rowptr[NN+1];
__device__ int   g_wptr[NN];

// ---------------- helpers -------------------------------------------------
__device__ __forceinline__ uint32_t cvt_tf32(float f) {
    uint32_t r;
    asm("cvt.rna.tf32.f32 %0, %1;" : "=r"(r) : "f"(f));
    return r;
}
__device__ __forceinline__ void mma8(float* c, const uint32_t* a, uint32_t b0, uint32_t b1) {
    asm("mma.sync.aligned.m16n8k8.row.col.f32.tf32.tf32.f32 "
        "{%0,%1,%2,%3}, {%4,%5,%6,%7}, {%8,%9}, {%0,%1,%2,%3};"
        : "+f"(c[0]), "+f"(c[1]), "+f"(c[2]), "+f"(c[3])
        : "r"(a[0]), "r"(a[1]), "r"(a[2]), "r"(a[3]), "r"(b0), "r"(b1));
}

// ---------------- CSR build ----------------------------------------------
__global__ void zero_deg_kernel() {
    int i = blockIdx.x*blockDim.x + threadIdx.x;
    if (i < NN) g_deg[i] = 0;
}

__global__ void hist_kernel(const int* __restrict__ dst) {
    int i = blockIdx.x*blockDim.x + threadIdx.x;
    if (i < EE) atomicAdd(&g_deg[dst[i]], 1);
}

__global__ void scan_kernel() {
    __shared__ int sh[1024];
    int t = threadIdx.x;
    const int ITEMS = (NN + 1023) / 1024;   // 49
    int base = t * ITEMS;
    int s = 0;
    for (int i = 0; i < ITEMS; i++) {
        int idx = base + i;
        if (idx < NN) s += g_deg[idx];
    }
    sh[t] = s;
    __syncthreads();
    for (int off = 1; off < 1024; off <<= 1) {
        int v = (t >= off) ? sh[t - off] : 0;
        __syncthreads();
        sh[t] += v;
        __syncthreads();
    }
    int run = sh[t] - s;   // exclusive prefix
    for (int i = 0; i < ITEMS; i++) {
        int idx = base + i;
        if (idx < NN) {
            g_rowptr[idx] = run;
            g_wptr[idx]   = run;
            run += g_deg[idx];
        }
    }
    if (t == 0) g_rowptr[NN] = EE;
}

__global__ void scatter_kernel(const int* __restrict__ src, const int* __restrict__ dst) {
    int i = blockIdx.x*blockDim.x + threadIdx.x;
    if (i < EE) {
        int d = dst[i];
        int p = atomicAdd(&g_wptr[d], 1);
        g_srcs[p] = src[i];
    }
}

// ------------- tf32x3 tensor-core GEMM, fragment-layout smem -------------
// C(Mx Ncols) = A(Mx128)@B(128xNcols) [+bias][+leaky 0.01]; Ncols%128==0.
// al != nullptr: attention dots for head hh=blockIdx.x -> g_el/g_er.
__global__ __launch_bounds__(256, 2)
void tf32gemm_kernel(const float* __restrict__ A, const float* __restrict__ B,
                     const float* __restrict__ bias, float* __restrict__ C,
                     int M, int Ncols, int act,
                     const float* __restrict__ al, const float* __restrict__ ar)
{
    __shared__ __align__(16) uint32_t As[2*A_PL];
    __shared__ __align__(16) uint32_t Bs[2*B_PL];
    __shared__ float sEl[2][BM], sEr[2][BM];

    int tid  = threadIdx.x;
    int lane = tid & 31, warp = tid >> 5;
    int wm = warp >> 1, wn = warp & 1;        // 4 x 2 warp grid, tile 32x64
    int m0 = blockIdx.y * BM, col0 = blockIdx.x * BN;

    float acc[2][8][4];
    #pragma unroll
    for (int i = 0; i < 2; i++)
        #pragma unroll
        for (int j = 0; j < 8; j++)
            #pragma unroll
            for (int q = 0; q < 4; q++) acc[i][j][q] = 0.f;

    // writer index maps
    int am = tid >> 1, akh = tid & 1;          // A: row, k-half (8 elems)
    int bn4 = tid & 31, bk = tid >> 5;         // B: n-quad, k row (and +8)

    // precomputed A writer addresses (8 elements, 2 planes share offset)
    int a_wm = am >> 5, a_mt = (am >> 4) & 1, a_r16 = am & 15;
    int a_blk = (a_wm*2 + akh)*2 + a_mt;
    int a_regbase = a_r16 >> 3;               // +2 if k8>=4
    int a_lanebase = (a_r16 & 7)*4;
    // B writer
    int b_reg = bk >> 2;                       // k8 = bk for both rows
    int b_k3 = bk & 3;

    const float4 z4 = make_float4(0.f,0.f,0.f,0.f);
    float4 aL0, aL1, bL0, bL1;
    {   // prefetch chunk 0
        int gr = m0 + am;
        const float* ap = &A[(size_t)gr*128 + akh*8];
        aL0 = (gr < M) ? *(const float4*)ap       : z4;
        aL1 = (gr < M) ? *(const float4*)(ap + 4) : z4;
        bL0 = *(const float4*)&B[bk*Ncols + col0 + bn4*4];
        bL1 = *(const float4*)&B[(bk+8)*Ncols + col0 + bn4*4];
    }

    #pragma unroll 1
    for (int ch = 0; ch < 8; ch++) {
        if (ch) __syncthreads();
        {   // ---- split + store A in fragment layout ----
            float v[8] = {aL0.x,aL0.y,aL0.z,aL0.w, aL1.x,aL1.y,aL1.z,aL1.w};
            uint32_t* basep = &As[a_blk*A_BLK];
            #pragma unroll
            for (int e = 0; e < 8; e++) {
                uint32_t hi = cvt_tf32(v[e]);
                uint32_t lo = cvt_tf32(v[e] - __uint_as_float(hi));
                int off = a_lanebase*4 + (e & 3)*4 + a_regbase + ((e >> 2) << 1);
                basep[off]        = hi;
                basep[A_PL + off] = lo;
            }
            // ---- split + store B (rows bk, bk+8 of chunk) ----
            float w0[4] = {bL0.x,bL0.y,bL0.z,bL0.w};
            float w1[4] = {bL1.x,bL1.y,bL1.z,bL1.w};
            #pragma unroll
            for (int e = 0; e < 4; e++) {
                int n = bn4*4 + e;
                int wnn = n >> 6, nt = (n >> 3) & 7, n8 = n & 7;
                int off0 = (wnn*2 + 0)*B_KS + nt*B_NT + (n8*4 + b_k3)*2 + b_reg;
                int off1 = (wnn*2 + 1)*B_KS + nt*B_NT + (n8*4 + b_k3)*2 + b_reg;
                uint32_t h0 = cvt_tf32(w0[e]);
                uint32_t l0 = cvt_tf32(w0[e] - __uint_as_float(h0));
                uint32_t h1 = cvt_tf32(w1[e]);
                uint32_t l1 = cvt_tf32(w1[e] - __uint_as_float(h1));
                Bs[off0]        = h0;
                Bs[B_PL + off0] = l0;
                Bs[off1]        = h1;
                Bs[B_PL + off1] = l1;
            }
        }
        __syncthreads();
        if (ch < 7) {   // prefetch next chunk (overlaps mma)
            int k0 = (ch + 1) * BK;
            int gr = m0 + am;
            const float* ap = &A[(size_t)gr*128 + k0 + akh*8];
            aL0 = (gr < M) ? *(const float4*)ap       : z4;
            aL1 = (gr < M) ? *(const float4*)(ap + 4) : z4;
            bL0 = *(const float4*)&B[(k0 + bk)*Ncols + col0 + bn4*4];
            bL1 = *(const float4*)&B[(k0 + bk + 8)*Ncols + col0 + bn4*4];
        }
        #pragma unroll
        for (int ks = 0; ks < 2; ks++) {
            uint4 ah[2], alo[2];
            #pragma unroll
            for (int mt = 0; mt < 2; mt++) {
                int blk = (wm*2 + ks)*2 + mt;
                ah[mt]  = *(const uint4*)&As[blk*A_BLK + lane*4];
                alo[mt] = *(const uint4*)&As[A_PL + blk*A_BLK + lane*4];
            }
            #pragma unroll
            for (int nt = 0; nt < 8; nt++) {
                int boff = (wn*2 + ks)*B_KS + nt*B_NT + lane*2;
                uint2 bh = *(const uint2*)&Bs[boff];
                uint2 bl = *(const uint2*)&Bs[B_PL + boff];
                #pragma unroll
                for (int mt = 0; mt < 2; mt++) {
                    mma8(acc[mt][nt], (const uint32_t*)&ah[mt],  bh.x, bh.y);
                    mma8(acc[mt][nt], (const uint32_t*)&ah[mt],  bl.x, bl.y);
                    mma8(acc[mt][nt], (const uint32_t*)&alo[mt], bh.x, bh.y);
                }
            }
        }
    }

    // ---------------- epilogue: store C ----------------------------------
    #pragma unroll
    for (int mt = 0; mt < 2; mt++) {
        #pragma unroll
        for (int half = 0; half < 2; half++) {
            int r = m0 + wm*32 + mt*16 + (lane >> 2) + half*8;
            if (r >= M) continue;
            #pragma unroll
            for (int nt = 0; nt < 8; nt++) {
                int c = col0 + wn*64 + nt*8 + 2*(lane & 3);
                float v0 = acc[mt][nt][half*2 + 0];
                float v1 = acc[mt][nt][half*2 + 1];
                if (bias) { v0 += bias[c]; v1 += bias[c+1]; }
                if (act)  { v0 = v0 > 0.f ? v0 : 0.01f*v0;
                            v1 = v1 > 0.f ? v1 : 0.01f*v1; }
                *(float2*)&C[(size_t)r*Ncols + c] = make_float2(v0, v1);
            }
        }
    }

    // ---------------- fused attention dots (GAT path) --------------------
    if (al) {
        int hh = blockIdx.x;
        float alv[8][2], arv[8][2];
        #pragma unroll
        for (int nt = 0; nt < 8; nt++)
            #pragma unroll
            for (int j = 0; j < 2; j++) {
                int c = wn*64 + nt*8 + 2*(lane & 3) + j;
                alv[nt][j] = __ldg(&al[hh*HIDN + c]);
                arv[nt][j] = __ldg(&ar[hh*HIDN + c]);
            }
        #pragma unroll
        for (int mt = 0; mt < 2; mt++) {
            #pragma unroll
            for (int half = 0; half < 2; half++) {
                float pl = 0.f, pr = 0.f;
                #pragma unroll
                for (int nt = 0; nt < 8; nt++)
                    #pragma unroll
                    for (int j = 0; j < 2; j++) {
                        float v = acc[mt][nt][half*2 + j];
                        pl += v * alv[nt][j];
                        pr += v * arv[nt][j];
                    }
                pl += __shfl_xor_sync(0xffffffffu, pl, 1);
                pl += __shfl_xor_sync(0xffffffffu, pl, 2);
                pr += __shfl_xor_sync(0xffffffffu, pr, 1);
                pr += __shfl_xor_sync(0xffffffffu, pr, 2);
                if ((lane & 3) == 0) {
                    int rl = wm*32 + mt*16 + (lane >> 2) + half*8;
                    sEl[wn][rl] = pl;
                    sEr[wn][rl] = pr;
                }
            }
        }
        __syncthreads();
        if (tid < BM) {
            int r = m0 + tid;
            if (r < M) {
                g_el[r*HH + hh] = sEl[0][tid] + sEl[1][tid];
                g_er[r*HH + hh] = sEr[0][tid] + sEr[1][tid];
            }
        }
    }
}

// ---------------- fused edge logits + softmax, warp per (dst,head) -------
__global__ void edge_softmax_kernel()
{
    int gw   = (blockIdx.x*blockDim.x + threadIdx.x) >> 5;
    int lane = threadIdx.x & 31;
    if (gw >= NN*HH) return;
    int n = gw / HH, hh = gw % HH;
    int beg = g_rowptr[n], end = g_rowptr[n+1];
    if (beg == end) return;
    float er_n = g_er[n*HH + hh];
    float* ap = &g_alpha[hh*EE];
    float mx = -1e30f;
    for (int j = beg + lane; j < end; j += 32) {
        int s = g_srcs[j];
        float v = g_el[s*HH + hh] + er_n;
        v = v > 0.f ? v : 0.2f*v;
        ap[j] = v;
        mx = fmaxf(mx, v);
    }
    #pragma unroll
    for (int o = 16; o; o >>= 1) mx = fmaxf(mx, __shfl_xor_sync(0xffffffffu, mx, o));
    float s = 0.f;
    for (int j = beg + lane; j < end; j += 32) {
        float e = expf(ap[j] - mx);
        ap[j] = e;
        s += e;
    }
    #pragma unroll
    for (int o = 16; o; o >>= 1) s += __shfl_xor_sync(0xffffffffu, s, o);
    if (lane == 0) g_dnm[n*HH + hh] = 1.f / (s + 1e-9f);
}

// ------ aggregation: warp per head, float4 per lane, head-mean -> g_x ----
__global__ __launch_bounds__(96)
void aggregate_kernel(const float* __restrict__ bias)
{
    __shared__ float4 sh[3][32];
    int n = blockIdx.x;
    int t = threadIdx.x;
    int head = t >> 5, lane = t & 31;
    int beg = g_rowptr[n], end = g_rowptr[n+1];

    const float* hb = &g_h[(size_t)head*HIDN + lane*4];
    const float* wp = &g_alpha[head*EE];

    float4 a = make_float4(0.f, 0.f, 0.f, 0.f);
    int j = beg;
    // unrolled by 2 with prefetch
    if (j + 1 < end) {
        int   s0 = g_srcs[j],   s1 = g_srcs[j+1];
        float w0 = __ldg(&wp[j]), w1 = __ldg(&wp[j+1]);
        for (; j + 3 < end; j += 2) {
            int   ns0 = g_srcs[j+2],   ns1 = g_srcs[j+3];
            float nw0 = __ldg(&wp[j+2]), nw1 = __ldg(&wp[j+3]);
            float4 v0 = *(const float4*)&hb[(size_t)s0*HF];
            float4 v1 = *(const float4*)&hb[(size_t)s1*HF];
            a.x += w0*v0.x + w1*v1.x;
            a.y += w0*v0.y + w1*v1.y;
            a.z += w0*v0.z + w1*v1.z;
            a.w += w0*v0.w + w1*v1.w;
            s0 = ns0; s1 = ns1; w0 = nw0; w1 = nw1;
        }
        float4 v0 = *(const float4*)&hb[(size_t)s0*HF];
        float4 v1 = *(const float4*)&hb[(size_t)s1*HF];
        a.x += w0*v0.x + w1*v1.x;
        a.y += w0*v0.y + w1*v1.y;
        a.z += w0*v0.z + w1*v1.z;
        a.w += w0*v0.w + w1*v1.w;
        j += 2;
    }
    for (; j < end; j++) {
        int s = g_srcs[j];
        float w = __ldg(&wp[j]);
        float4 v = *(const float4*)&hb[(size_t)s*HF];
        a.x += w*v.x; a.y += w*v.y; a.z += w*v.z; a.w += w*v.w;
    }

    float dnm = g_dnm[n*HH + head];
    const float4 b4 = *(const float4*)&bias[head*HIDN + lane*4];
    a.x = a.x*dnm + b4.x;  a.y = a.y*dnm + b4.y;
    a.z = a.z*dnm + b4.z;  a.w = a.w*dnm + b4.w;
    a.x = a.x > 0.f ? a.x : 0.01f*a.x;
    a.y = a.y > 0.f ? a.y : 0.01f*a.y;
    a.z = a.z > 0.f ? a.z : 0.01f*a.z;
    a.w = a.w > 0.f ? a.w : 0.01f*a.w;
    sh[head][lane] = a;
    __syncthreads();
    if (t < 32) {
        float4 r0 = sh[0][t], r1 = sh[1][t], r2 = sh[2][t];
        float4 o;
        o.x = (r0.x + r1.x + r2.x) * (1.f/3.f);
        o.y = (r0.y + r1.y + r2.y) * (1.f/3.f);
        o.z = (r0.z + r1.z + r2.z) * (1.f/3.f);
        o.w = (r0.w + r1.w + r2.w) * (1.f/3.f);
        *(float4*)&g_x[(size_t)n*HIDN + t*4] = o;
    }
}

// ---------------- classifier: (N,128)@(128,6)+b, warp per node -----------
__global__ void classifier_kernel(const float* __restrict__ lw5, const float* __restrict__ lb5,
                                  float* __restrict__ out)
{
    int gw   = (blockIdx.x*blockDim.x + threadIdx.x) >> 5;
    int lane = threadIdx.x & 31;
    if (gw >= NN) return;
    const float* xr = &g_x[(size_t)gw*HIDN];
    float acc[NCLS] = {};
    #pragma unroll
    for (int k = lane; k < HIDN; k += 32) {
        float xv = xr[k];
        #pragma unroll
        for (int c = 0; c < NCLS; c++) acc[c] += xv * __ldg(&lw5[k*NCLS + c]);
    }
    #pragma unroll
    for (int c = 0; c < NCLS; c++)
        #pragma unroll
        for (int o = 16; o; o >>= 1) acc[c] += __shfl_xor_sync(0xffffffffu, acc[c], o);
    if (lane == 0) {
        #pragma unroll
        for (int c = 0; c < NCLS; c++) out[gw*NCLS + c] = acc[c] + lb5[c];
    }
}

// -------------------------------------------------------------------------
extern "C" void kernel_launch(void* const* d_in, const int* in_sizes, int n_in,
                              void* d_out, int out_size)
{
    const float* in_feat = (const float*)d_in[0];
    const int*   src     = (const int*)  d_in[1];
    const int*   dst     = (const int*)  d_in[2];
    const float* W1  = (const float*)d_in[3];
    const float* al1 = (const float*)d_in[4];
    const float* ar1 = (const float*)d_in[5];
    const float* b1  = (const float*)d_in[6];
    const float* W2  = (const float*)d_in[7];
    const float* al2 = (const float*)d_in[8];
    const float* ar2 = (const float*)d_in[9];
    const float* b2  = (const float*)d_in[10];
    const float* lw1 = (const float*)d_in[11];
    const float* lb1 = (const float*)d_in[12];
    const float* lw2 = (const float*)d_in[13];
    const float* lb2 = (const float*)d_in[14];
    const float* lw3 = (const float*)d_in[15];
    const float* lb3 = (const float*)d_in[16];
    const float* lw4 = (const float*)d_in[17];
    const float* lb4 = (const float*)d_in[18];
    const float* lw5 = (const float*)d_in[19];
    const float* lb5 = (const float*)d_in[20];
    float* out = (float*)d_out;

    float *ph, *px, *py;
    cudaGetSymbolAddress((void**)&ph, g_h);
    cudaGetSymbolAddress((void**)&px, g_x);
    cudaGetSymbolAddress((void**)&py, g_y);

    const int TB = 256;
    int warp_blocks = (NN*HH + 7) / 8;   // 8 warps per 256-thread block

    // CSR build (shared by both layers)
    zero_deg_kernel<<<(NN + TB - 1)/TB, TB>>>();
    hist_kernel<<<(EE + TB - 1)/TB, TB>>>(dst);
    scan_kernel<<<1, 1024>>>();
    scatter_kernel<<<(EE + TB - 1)/TB, TB>>>(src, dst);

    dim3 g_gat(HF/BN, (NN + BM - 1)/BM);     // (3, 391)
    dim3 g_mlp(HIDN/BN, (NN + BM - 1)/BM);   // (1, 391)

    // ---- GAT layer 1 ----
    tf32gemm_kernel<<<g_gat, 256>>>(in_feat, W1, nullptr, ph, NN, HF, 0, al1, ar1);
    edge_softmax_kernel<<<warp_blocks, 256>>>();
    aggregate_kernel<<<NN, 96>>>(b1);

    // ---- GAT layer 2 ----
    tf32gemm_kernel<<<g_gat, 256>>>(px, W2, nullptr, ph, NN, HF, 0, al2, ar2);
    edge_softmax_kernel<<<warp_blocks, 256>>>();
    aggregate_kernel<<<NN, 96>>>(b2);

    // ---- MLP head ----
    tf32gemm_kernel<<<g_mlp, 256>>>(px, lw1, lb1, py, NN, HIDN, 1, nullptr, nullptr);
    tf32gemm_kernel<<<g_mlp, 256>>>(py, lw2, lb2, px, NN, HIDN, 1, nullptr, nullptr);
    tf32gemm_kernel<<<g_mlp, 256>>>(px, lw3, lb3, py, NN, HIDN, 1, nullptr, nullptr);
    tf32gemm_kernel<<<g_mlp, 256>>>(py, lw4, lb4, px, NN, HIDN, 1, nullptr, nullptr);
    classifier_kernel<<<(NN + 7)/8, 256>>>(lw5, lb5, out);
}